// round 3
// baseline (speedup 1.0000x reference)
#include <cuda_runtime.h>
#include <math.h>

#define NB 8
#define NC 128
#define NN 20000
#define TN 128
#define NT ((NN + TN - 1) / TN)   // 157
#define TN1 (TN + 1)              // padded row stride
#define EPSV 1e-5f
#define INVTEMP 0.08838834764831845f  // 1/sqrt(128)

// Scratch (static __device__ arrays: allocation-free per harness rules)
__device__ float g_v[(size_t)NB * NC * NN];      // ~82 MB
__device__ float g_attn[(size_t)NB * NC * NC];   // 512 KB
__device__ float g_par[11 * NC];                 // folded BN / graph-context params

// shared-memory float offsets for proj_attn_kernel
#define OFF_PC 0          // [128][129]
#define OFF_QS 16512      // [128][129]
#define OFF_KG 33024      // [128][129]
#define OFF_WS 49536      // [16][129]
#define OFF_PAR 51600     // 11 x 128
#define OFF_X  53008      // [4][128]
#define SMEM_B_FLOATS 53520
#define SMEM_B_BYTES (SMEM_B_FLOATS * 4)

#define SMEM_D_FLOATS (2 * 16512)
#define SMEM_D_BYTES (SMEM_D_FLOATS * 4)

// ---- one-time parameter folding: 1 block, 128 threads ----
__global__ void prep_kernel(const float* __restrict__ gq, const float* __restrict__ bq,
                            const float* __restrict__ mq, const float* __restrict__ vq,
                            const float* __restrict__ gk, const float* __restrict__ bk,
                            const float* __restrict__ mk, const float* __restrict__ vk,
                            const float* __restrict__ gv, const float* __restrict__ bv,
                            const float* __restrict__ mv, const float* __restrict__ vv,
                            const float* __restrict__ Wg1, const float* __restrict__ bg1,
                            const float* __restrict__ Wg2, const float* __restrict__ bg2)
{
    int o = threadIdx.x;
    float s;
    s = gq[o] * rsqrtf(vq[o] + EPSV); g_par[o]       = s; g_par[128 + o] = bq[o] - mq[o] * s;
    s = gk[o] * rsqrtf(vk[o] + EPSV); g_par[256 + o] = s; g_par[384 + o] = bk[o] - mk[o] * s;
    s = gv[o] * rsqrtf(vv[o] + EPSV); g_par[512 + o] = s; g_par[640 + o] = bv[o] - mv[o] * s;
    g_par[768 + o]  = Wg1[o * 2];
    g_par[896 + o]  = Wg1[o * 2 + 1];
    g_par[1024 + o] = Wg2[o * 2];
    g_par[1152 + o] = Wg2[o * 2 + 1];
    g_par[1280 + o] = bg1[o] + bg2[o];
    for (int idx = threadIdx.x; idx < NB * NC * NC; idx += blockDim.x)
        g_attn[idx] = 0.f;
}

// 128x128 (out) x 128 (k) GEMM: acc[i][j] += W[o][c] * pc_s[c][n]
__device__ __forceinline__ void gemm128(const float* __restrict__ Wp,
                                        const float* pc_s, float* ws,
                                        int tx, int ty, int tid,
                                        float acc[8][8])
{
#pragma unroll
    for (int i = 0; i < 8; i++)
#pragma unroll
        for (int j = 0; j < 8; j++) acc[i][j] = 0.f;

    for (int kk = 0; kk < NC; kk += 16) {
        __syncthreads();   // protect ws from previous consumers
#pragma unroll
        for (int l = 0; l < 8; l++) {
            int idx = tid + l * 256;
            int o = idx >> 4;
            int cc = idx & 15;
            ws[cc * 129 + o] = Wp[o * NC + kk + cc];   // coalesced gmem read
        }
        __syncthreads();
#pragma unroll 4
        for (int cc = 0; cc < 16; cc++) {
            float av[8], bw[8];
#pragma unroll
            for (int i = 0; i < 8; i++) av[i] = ws[cc * 129 + ty + i * 16];
#pragma unroll
            for (int j = 0; j < 8; j++) bw[j] = pc_s[(kk + cc) * TN1 + tx + j * 16];
#pragma unroll
            for (int i = 0; i < 8; i++)
#pragma unroll
                for (int j = 0; j < 8; j++)
                    acc[i][j] = fmaf(av[i], bw[j], acc[i][j]);
        }
    }
}

__global__ __launch_bounds__(256, 1)
void proj_attn_kernel(const float* __restrict__ pc, const float* __restrict__ xin,
                      const float* __restrict__ Wq, const float* __restrict__ Wk,
                      const float* __restrict__ Wv)
{
    extern __shared__ float sm[];
    float* pc_s = sm + OFF_PC;
    float* qs_s = sm + OFF_QS;
    float* kg_s = sm + OFF_KG;
    float* ws   = sm + OFF_WS;
    float* par  = sm + OFF_PAR;
    float* x_s  = sm + OFF_X;

    const int tid = threadIdx.x;
    const int tx = tid & 15;
    const int ty = tid >> 4;
    const int tile = blockIdx.x;
    const int b = blockIdx.y;
    const int n0 = tile * TN;
    const bool full = (n0 + TN <= NN);

    for (int idx = tid; idx < 11 * NC; idx += 256)
        par[idx] = g_par[idx];

    // load pc tile [128][TN]
    if (full) {
        // vectorized: each row of 128 floats = 32 float4
        for (int idx = tid; idx < NC * (TN / 4); idx += 256) {
            int c = idx >> 5;
            int q4 = idx & 31;
            float4 val = *(const float4*)(pc + ((size_t)b * NC + c) * NN + n0 + q4 * 4);
            float* dst = pc_s + c * TN1 + q4 * 4;
            dst[0] = val.x; dst[1] = val.y; dst[2] = val.z; dst[3] = val.w;
        }
    } else {
        for (int idx = tid; idx < NC * TN; idx += 256) {
            int c = idx >> 7;
            int nn = idx & 127;
            int n = n0 + nn;
            pc_s[c * TN1 + nn] = (n < NN) ? pc[((size_t)b * NC + c) * NN + n] : 0.f;
        }
    }
    // load x tile [4][TN]
    for (int idx = tid; idx < 4 * TN; idx += 256) {
        int ch = idx >> 7;
        int nn = idx & 127;
        int n = n0 + nn;
        x_s[ch * TN + nn] = (n < NN) ? xin[((size_t)b * 4 + ch) * NN + n] : 0.f;
    }
    __syncthreads();

    float acc[8][8];

    // ---- q projection -> qs_s (BN + relu + /temp) ----
    gemm128(Wq, pc_s, ws, tx, ty, tid, acc);
#pragma unroll
    for (int i = 0; i < 8; i++) {
        int o = ty + i * 16;
        float sc = par[o], sh = par[128 + o];
#pragma unroll
        for (int j = 0; j < 8; j++) {
            int nn = tx + j * 16;
            float val = fmaxf(fmaf(acc[i][j], sc, sh), 0.f) * INVTEMP;
            if (n0 + nn >= NN) val = 0.f;
            qs_s[o * TN1 + nn] = val;
        }
    }

    // ---- k projection + graph context -> kg_s ----
    gemm128(Wk, pc_s, ws, tx, ty, tid, acc);
#pragma unroll
    for (int i = 0; i < 8; i++) {
        int o = ty + i * 16;
        float sc = par[256 + o], sh = par[384 + o];
        float w10 = par[768 + o], w11 = par[896 + o];
        float w20 = par[1024 + o], w21 = par[1152 + o];
        float bgg = par[1280 + o];
#pragma unroll
        for (int j = 0; j < 8; j++) {
            int nn = tx + j * 16;
            float val = fmaxf(fmaf(acc[i][j], sc, sh), 0.f);
            float gc = fmaf(w10, x_s[nn],
                        fmaf(w11, x_s[128 + nn],
                         fmaf(w20, x_s[256 + nn],
                          fmaf(w21, x_s[384 + nn], bgg))));
            val += gc;
            if (n0 + nn >= NN) val = 0.f;
            kg_s[o * TN1 + nn] = val;
        }
    }

    // ---- v projection -> global scratch ----
    gemm128(Wv, pc_s, ws, tx, ty, tid, acc);
#pragma unroll
    for (int i = 0; i < 8; i++) {
        int o = ty + i * 16;
        float sc = par[512 + o], sh = par[640 + o];
#pragma unroll
        for (int j = 0; j < 8; j++) {
            int nn = tx + j * 16;
            int n = n0 + nn;
            if (n < NN) {
                float val = fmaxf(fmaf(acc[i][j], sc, sh), 0.f);
                g_v[((size_t)b * NC + o) * NN + n] = val;
            }
        }
    }

    // ---- attn partial: acc[c][d] = sum_n qs_s[c][n] * kg_s[d][n] ----
    __syncthreads();
#pragma unroll
    for (int i = 0; i < 8; i++)
#pragma unroll
        for (int j = 0; j < 8; j++) acc[i][j] = 0.f;

#pragma unroll 4
    for (int n = 0; n < TN; n++) {
        float av[8], bw[8];
#pragma unroll
        for (int i = 0; i < 8; i++) av[i] = qs_s[(ty + i * 16) * TN1 + n];
#pragma unroll
        for (int j = 0; j < 8; j++) bw[j] = kg_s[(tx + j * 16) * TN1 + n];
#pragma unroll
        for (int i = 0; i < 8; i++)
#pragma unroll
            for (int j = 0; j < 8; j++)
                acc[i][j] = fmaf(av[i], bw[j], acc[i][j]);
    }

#pragma unroll
    for (int i = 0; i < 8; i++) {
        int c = ty + i * 16;
#pragma unroll
        for (int j = 0; j < 8; j++) {
            int d = tx + j * 16;
            atomicAdd(&g_attn[((size_t)b * NC + c) * NC + d], acc[i][j]);
        }
    }
}

__global__ void softmax_kernel()
{
    __shared__ float red[NC];
    const int row = blockIdx.x;          // b*C + c
    const int t = threadIdx.x;           // d
    float* a = g_attn + (size_t)row * NC;
    float v = a[t];
    red[t] = v;
    __syncthreads();
    for (int s = 64; s > 0; s >>= 1) {
        if (t < s) red[t] = fmaxf(red[t], red[t + s]);
        __syncthreads();
    }
    float mx = red[0];
    __syncthreads();
    float e = expf(v - mx);
    red[t] = e;
    __syncthreads();
    for (int s = 64; s > 0; s >>= 1) {
        if (t < s) red[t] += red[t + s];
        __syncthreads();
    }
    float inv = 1.f / red[0];
    a[t] = e * inv;
}

__global__ __launch_bounds__(256, 1)
void out_kernel(float* __restrict__ out)
{
    extern __shared__ float sm[];
    float* a_s = sm;           // [128][129] softmaxed attn
    float* v_s = sm + 16512;   // [128][129] v tile

    const int tid = threadIdx.x;
    const int tx = tid & 15;
    const int ty = tid >> 4;
    const int tile = blockIdx.x;
    const int b = blockIdx.y;
    const int n0 = tile * TN;
    const bool full = (n0 + TN <= NN);

    for (int idx = tid; idx < NC * NC; idx += 256) {
        int c = idx >> 7;
        int d = idx & 127;
        a_s[c * TN1 + d] = g_attn[(size_t)b * NC * NC + idx];
    }
    if (full) {
        for (int idx = tid; idx < NC * (TN / 4); idx += 256) {
            int d = idx >> 5;
            int q4 = idx & 31;
            float4 val = *(const float4*)(g_v + ((size_t)b * NC + d) * NN + n0 + q4 * 4);
            float* dst = v_s + d * TN1 + q4 * 4;
            dst[0] = val.x; dst[1] = val.y; dst[2] = val.z; dst[3] = val.w;
        }
    } else {
        for (int idx = tid; idx < NC * TN; idx += 256) {
            int d = idx >> 7;
            int nn = idx & 127;
            int n = n0 + nn;
            v_s[d * TN1 + nn] = (n < NN) ? g_v[((size_t)b * NC + d) * NN + n] : 0.f;
        }
    }
    __syncthreads();

    float acc[8][8];
#pragma unroll
    for (int i = 0; i < 8; i++)
#pragma unroll
        for (int j = 0; j < 8; j++) acc[i][j] = 0.f;

#pragma unroll 4
    for (int d = 0; d < NC; d++) {
        float av[8], bw[8];
#pragma unroll
        for (int i = 0; i < 8; i++) av[i] = a_s[(ty + i * 16) * TN1 + d];
#pragma unroll
        for (int j = 0; j < 8; j++) bw[j] = v_s[d * TN1 + tx + j * 16];
#pragma unroll
        for (int i = 0; i < 8; i++)
#pragma unroll
            for (int j = 0; j < 8; j++)
                acc[i][j] = fmaf(av[i], bw[j], acc[i][j]);
    }

#pragma unroll
    for (int i = 0; i < 8; i++) {
        int c = ty + i * 16;
#pragma unroll
        for (int j = 0; j < 8; j++) {
            int nn = tx + j * 16;
            int n = n0 + nn;
            if (n < NN)
                out[((size_t)b * NC + c) * NN + n] = acc[i][j];
        }
    }
}

extern "C" void kernel_launch(void* const* d_in, const int* in_sizes, int n_in,
                              void* d_out, int out_size)
{
    const float* pc  = (const float*)d_in[0];
    const float* x   = (const float*)d_in[1];
    const float* Wq  = (const float*)d_in[2];
    const float* gq  = (const float*)d_in[3];
    const float* bq  = (const float*)d_in[4];
    const float* mq  = (const float*)d_in[5];
    const float* vq  = (const float*)d_in[6];
    const float* Wk  = (const float*)d_in[7];
    const float* gk  = (const float*)d_in[8];
    const float* bk  = (const float*)d_in[9];
    const float* mk  = (const float*)d_in[10];
    const float* vk  = (const float*)d_in[11];
    const float* Wv  = (const float*)d_in[12];
    const float* gv  = (const float*)d_in[13];
    const float* bv  = (const float*)d_in[14];
    const float* mv  = (const float*)d_in[15];
    const float* vv  = (const float*)d_in[16];
    const float* Wg1 = (const float*)d_in[17];
    const float* bg1 = (const float*)d_in[18];
    const float* Wg2 = (const float*)d_in[19];
    const float* bg2 = (const float*)d_in[20];
    float* out = (float*)d_out;

    cudaFuncSetAttribute(proj_attn_kernel,
                         cudaFuncAttributeMaxDynamicSharedMemorySize, SMEM_B_BYTES);
    cudaFuncSetAttribute(out_kernel,
                         cudaFuncAttributeMaxDynamicSharedMemorySize, SMEM_D_BYTES);

    prep_kernel<<<1, NC>>>(gq, bq, mq, vq, gk, bk, mk, vk, gv, bv, mv, vv,
                           Wg1, bg1, Wg2, bg2);

    dim3 grid(NT, NB);
    proj_attn_kernel<<<grid, 256, SMEM_B_BYTES>>>(pc, x, Wq, Wk, Wv);
    softmax_kernel<<<NB * NC, NC>>>();
    out_kernel<<<grid, 256, SMEM_D_BYTES>>>(out);
}

// round 4
// speedup vs baseline: 1.1540x; 1.1540x over previous
#include <cuda_runtime.h>
#include <math.h>

#define NB 8
#define NC 128
#define NN 20000
#define TN 128
#define NT 157
#define SROW 132
#define EPSV 1e-5f
#define INVTEMP 0.08838834764831845f  // 1/sqrt(128)

// Scratch (static __device__ arrays: allocation-free per harness rules)
__device__ float g_v[(size_t)NB * NC * NN];      // ~82 MB, layout [b][d][n]
__device__ float g_attn[(size_t)NB * NC * NC];   // 512 KB
__device__ float g_par[11 * NC];                 // folded BN / graph-context params

// proj_attn smem float offsets
#define OFF_PC 0          // pc   [128][132]
#define OFF_QS 16896      // qs   [128][132]
#define OFF_KG 33792      // kg   [128][132] (swizzled rows)
#define OFF_WD 50688      // wdup [16][260]
#define OFF_PAR 54848     // 11*128
#define OFF_X  56256      // [4][128]
#define SMEM_A_FLOATS 56768
#define SMEM_A_BYTES (SMEM_A_FLOATS * 4)   // 227072 B

// out_kernel smem
#define OFF_AD 0          // a_dup [128][260]
#define OFF_VS 33280      // v     [128][132]
#define SMEM_O_FLOATS 50176
#define SMEM_O_BYTES (SMEM_O_FLOATS * 4)   // 200704 B

typedef unsigned long long u64;
typedef unsigned int u32;

__device__ __forceinline__ u64 pk2(float lo, float hi) {
    u64 r; asm("mov.b64 %0,{%1,%2};" : "=l"(r) : "f"(lo), "f"(hi)); return r;
}
__device__ __forceinline__ float2 upk2(u64 v) {
    float2 r; asm("mov.b64 {%0,%1},%2;" : "=f"(r.x), "=f"(r.y) : "l"(v)); return r;
}
__device__ __forceinline__ void fma2(u64& d, u64 a, u64 b) {
    asm("fma.rn.f32x2 %0,%1,%2,%0;" : "+l"(d) : "l"(a), "l"(b));
}
__device__ __forceinline__ u64 lds64(u32 a) {
    u64 r; asm volatile("ld.shared.b64 %0,[%1];" : "=l"(r) : "r"(a)); return r;
}
__device__ __forceinline__ void lds128(u64& x, u64& y, u32 a) {
    asm volatile("ld.shared.v2.u64 {%0,%1},[%2];" : "=l"(x), "=l"(y) : "r"(a));
}
__device__ __forceinline__ void sts64(u32 a, u64 v) {
    asm volatile("st.shared.b64 [%0],%1;" :: "r"(a), "l"(v));
}
__device__ __forceinline__ u32 smem_u32(const void* p) {
    u32 a;
    asm("{.reg .u64 t; cvta.to.shared.u64 t,%1; cvt.u32.u64 %0,t;}" : "=r"(a) : "l"(p));
    return a;
}

// ---- one-time parameter folding ----
__global__ void prep_kernel(const float* __restrict__ gq, const float* __restrict__ bq,
                            const float* __restrict__ mq, const float* __restrict__ vq,
                            const float* __restrict__ gk, const float* __restrict__ bk,
                            const float* __restrict__ mk, const float* __restrict__ vk,
                            const float* __restrict__ gv, const float* __restrict__ bv,
                            const float* __restrict__ mv, const float* __restrict__ vv,
                            const float* __restrict__ Wg1, const float* __restrict__ bg1,
                            const float* __restrict__ Wg2, const float* __restrict__ bg2)
{
    int o = threadIdx.x;
    float s;
    s = gq[o] * rsqrtf(vq[o] + EPSV); g_par[o]       = s; g_par[128 + o] = bq[o] - mq[o] * s;
    s = gk[o] * rsqrtf(vk[o] + EPSV); g_par[256 + o] = s; g_par[384 + o] = bk[o] - mk[o] * s;
    s = gv[o] * rsqrtf(vv[o] + EPSV); g_par[512 + o] = s; g_par[640 + o] = bv[o] - mv[o] * s;
    g_par[768 + o]  = Wg1[o * 2];
    g_par[896 + o]  = Wg1[o * 2 + 1];
    g_par[1024 + o] = Wg2[o * 2];
    g_par[1152 + o] = Wg2[o * 2 + 1];
    g_par[1280 + o] = bg1[o] + bg2[o];
    for (int idx = threadIdx.x; idx < NB * NC * NC; idx += blockDim.x)
        g_attn[idx] = 0.f;
}

// packed 128x128x128 GEMM: out rows o=8*ty+i, cols n packed pairs.
// acc[i][j] lanes = (sum_c W[o][c]*pc[c][n], ... pc[c][n+1]) with
// n = 4*tx + 64*(j>>1) + 2*(j&1).
__device__ __forceinline__ void gemm_f2(const float* __restrict__ Wp,
                                        u32 sPC, u32 sWD,
                                        int tx, int ty, int tid, u64 acc[8][4])
{
#pragma unroll
    for (int i = 0; i < 8; i++)
#pragma unroll
        for (int j = 0; j < 4; j++) acc[i][j] = 0ull;

    for (int kk = 0; kk < 8; kk++) {
        __syncthreads();   // protect wdup from previous consumers
#pragma unroll
        for (int l = 0; l < 2; l++) {
            int idx = tid + l * 256;
            int o = idx >> 2, cq = idx & 3;
            float4 w = *(const float4*)(Wp + o * NC + kk * 16 + cq * 4);
            u32 base = sWD + ((u32)(cq * 4) * 260 + 2 * o) * 4;
            sts64(base,             pk2(w.x, w.x));
            sts64(base + 260 * 4,   pk2(w.y, w.y));
            sts64(base + 2*260 * 4, pk2(w.z, w.z));
            sts64(base + 3*260 * 4, pk2(w.w, w.w));
        }
        __syncthreads();
#pragma unroll 4
        for (int cc = 0; cc < 16; cc++) {
            u64 a2[8], b2[4];
            u32 wb = sWD + (u32)(cc * 260 + 16 * ty) * 4;
#pragma unroll
            for (int i2 = 0; i2 < 4; i2++)
                lds128(a2[2 * i2], a2[2 * i2 + 1], wb + 16 * i2);
            u32 pb = sPC + (u32)((kk * 16 + cc) * SROW + 4 * tx) * 4;
            lds128(b2[0], b2[1], pb);
            lds128(b2[2], b2[3], pb + 64 * 4);
#pragma unroll
            for (int i = 0; i < 8; i++)
#pragma unroll
                for (int j = 0; j < 4; j++)
                    fma2(acc[i][j], a2[i], b2[j]);
        }
    }
}

__global__ __launch_bounds__(256, 1)
void proj_attn_kernel(const float* __restrict__ pc, const float* __restrict__ xin,
                      const float* __restrict__ Wq, const float* __restrict__ Wk,
                      const float* __restrict__ Wv)
{
    extern __shared__ float sm[];
    float* par = sm + OFF_PAR;
    float* x_s = sm + OFF_X;
    const u32 sbase = smem_u32(sm);
    const u32 sPC = sbase + OFF_PC * 4;
    const u32 sQS = sbase + OFF_QS * 4;
    const u32 sKG = sbase + OFF_KG * 4;
    const u32 sWD = sbase + OFF_WD * 4;
    const u32 sX  = sbase + OFF_X * 4;

    const int tid = threadIdx.x;
    const int tx = tid & 15;
    const int ty = tid >> 4;
    const int tile = blockIdx.x;
    const int b = blockIdx.y;
    const int n0 = tile * TN;
    const bool fullt = (n0 + TN <= NN);

    for (int idx = tid; idx < 11 * NC; idx += 256)
        par[idx] = g_par[idx];

    // load pc tile [128][TN] into stride-132 rows
    if (fullt) {
        for (int idx = tid; idx < NC * (TN / 4); idx += 256) {
            int c = idx >> 5, q = idx & 31;
            float4 val = *(const float4*)(pc + ((size_t)b * NC + c) * NN + n0 + q * 4);
            *(float4*)(sm + OFF_PC + c * SROW + q * 4) = val;
        }
    } else {
        for (int idx = tid; idx < NC * TN; idx += 256) {
            int c = idx >> 7, nn = idx & 127;
            int n = n0 + nn;
            sm[OFF_PC + c * SROW + nn] = (n < NN) ? pc[((size_t)b * NC + c) * NN + n] : 0.f;
        }
    }
    for (int idx = tid; idx < 4 * TN; idx += 256) {
        int ch = idx >> 7, nn = idx & 127;
        int n = n0 + nn;
        x_s[ch * 128 + nn] = (n < NN) ? xin[((size_t)b * 4 + ch) * NN + n] : 0.f;
    }
    // (gemm_f2's first __syncthreads orders these fills before use)

    u64 acc[8][4];

    // ---- q projection -> qs (BN + relu + /temp) ----
    gemm_f2(Wq, sPC, sWD, tx, ty, tid, acc);
#pragma unroll
    for (int i = 0; i < 8; i++) {
        int o = 8 * ty + i;
        float sc = par[o], sh = par[128 + o];
#pragma unroll
        for (int j = 0; j < 4; j++) {
            int nb = 4 * tx + 64 * (j >> 1) + 2 * (j & 1);
            float2 p = upk2(acc[i][j]);
            float v0 = fmaxf(fmaf(p.x, sc, sh), 0.f) * INVTEMP;
            float v1 = fmaxf(fmaf(p.y, sc, sh), 0.f) * INVTEMP;
            if (!fullt) {
                if (n0 + nb >= NN) v0 = 0.f;
                if (n0 + nb + 1 >= NN) v1 = 0.f;
            }
            sts64(sQS + (u32)(o * SROW + nb) * 4, pk2(v0, v1));
        }
    }

    // ---- k projection + graph context -> kg (swizzled rows) ----
    gemm_f2(Wk, sPC, sWD, tx, ty, tid, acc);
    {
        u64 xp[4][4];   // [ch][j]
#pragma unroll
        for (int j = 0; j < 4; j++) {
            int nb = 4 * tx + 64 * (j >> 1) + 2 * (j & 1);
#pragma unroll
            for (int ch = 0; ch < 4; ch++)
                xp[ch][j] = lds64(sX + (u32)(ch * 128 + nb) * 4);
        }
#pragma unroll
        for (int i = 0; i < 8; i++) {
            int o = 8 * ty + i;
            float sc = par[256 + o], sh = par[384 + o];
            u64 w0 = pk2(par[768 + o], par[768 + o]);
            u64 w1 = pk2(par[896 + o], par[896 + o]);
            u64 w2 = pk2(par[1024 + o], par[1024 + o]);
            u64 w3 = pk2(par[1152 + o], par[1152 + o]);
            float bgg = par[1280 + o];
            int rot = 4 * (o & 31);
#pragma unroll
            for (int j = 0; j < 4; j++) {
                int nb = 4 * tx + 64 * (j >> 1) + 2 * (j & 1);
                u64 g2 = pk2(bgg, bgg);
                fma2(g2, w0, xp[0][j]);
                fma2(g2, w1, xp[1][j]);
                fma2(g2, w2, xp[2][j]);
                fma2(g2, w3, xp[3][j]);
                float2 gc = upk2(g2);
                float2 p = upk2(acc[i][j]);
                float v0 = fmaxf(fmaf(p.x, sc, sh), 0.f) + gc.x;
                float v1 = fmaxf(fmaf(p.y, sc, sh), 0.f) + gc.y;
                if (!fullt) {
                    if (n0 + nb >= NN) v0 = 0.f;
                    if (n0 + nb + 1 >= NN) v1 = 0.f;
                }
                int phys = (nb + rot) & 127;
                sts64(sKG + (u32)(o * SROW + phys) * 4, pk2(v0, v1));
            }
        }
    }

    // ---- v projection -> g_v[b][d][n] ----
    gemm_f2(Wv, sPC, sWD, tx, ty, tid, acc);
#pragma unroll
    for (int i = 0; i < 8; i++) {
        int o = 8 * ty + i;
        float sc = par[512 + o], sh = par[640 + o];
#pragma unroll
        for (int j4 = 0; j4 < 2; j4++) {
            float2 pa = upk2(acc[i][2 * j4]);
            float2 pb = upk2(acc[i][2 * j4 + 1]);
            float4 v;
            v.x = fmaxf(fmaf(pa.x, sc, sh), 0.f);
            v.y = fmaxf(fmaf(pa.y, sc, sh), 0.f);
            v.z = fmaxf(fmaf(pb.x, sc, sh), 0.f);
            v.w = fmaxf(fmaf(pb.y, sc, sh), 0.f);
            int nb = 4 * tx + 64 * j4;
            size_t gaddr = ((size_t)b * NC + o) * NN + n0 + nb;
            if (fullt) {
                *(float4*)(g_v + gaddr) = v;
            } else {
                if (n0 + nb < NN)     g_v[gaddr]     = v.x;
                if (n0 + nb + 1 < NN) g_v[gaddr + 1] = v.y;
                if (n0 + nb + 2 < NN) g_v[gaddr + 2] = v.z;
                if (n0 + nb + 3 < NN) g_v[gaddr + 3] = v.w;
            }
        }
    }

    // ---- attn partial: reduction-packed over n ----
    __syncthreads();
    u64 at[8][8];
#pragma unroll
    for (int i = 0; i < 8; i++)
#pragma unroll
        for (int j = 0; j < 8; j++) at[i][j] = 0ull;

    for (int nq = 0; nq < 32; nq++) {
        u64 qa[8][2];
#pragma unroll
        for (int i = 0; i < 8; i++)
            lds128(qa[i][0], qa[i][1], sQS + (u32)((8 * ty + i) * SROW + 4 * nq) * 4);
#pragma unroll
        for (int h = 0; h < 2; h++) {
            u64 kb[4][2];
#pragma unroll
            for (int jj = 0; jj < 4; jj++) {
                int j = h * 4 + jj;
                int d = tx + 16 * j;
                int phys = (4 * nq + 4 * (d & 31)) & 127;
                lds128(kb[jj][0], kb[jj][1], sKG + (u32)(d * SROW + phys) * 4);
            }
#pragma unroll
            for (int i = 0; i < 8; i++)
#pragma unroll
                for (int jj = 0; jj < 4; jj++) {
                    fma2(at[i][h * 4 + jj], qa[i][0], kb[jj][0]);
                    fma2(at[i][h * 4 + jj], qa[i][1], kb[jj][1]);
                }
        }
    }

#pragma unroll
    for (int i = 0; i < 8; i++) {
        int c = 8 * ty + i;
#pragma unroll
        for (int j = 0; j < 8; j++) {
            int d = tx + 16 * j;
            float2 s = upk2(at[i][j]);
            atomicAdd(&g_attn[((size_t)b * NC + c) * NC + d], s.x + s.y);
        }
    }
}

__global__ void softmax_kernel()
{
    __shared__ float red[NC];
    const int row = blockIdx.x;
    const int t = threadIdx.x;
    float* a = g_attn + (size_t)row * NC;
    float v = a[t];
    red[t] = v;
    __syncthreads();
    for (int s = 64; s > 0; s >>= 1) {
        if (t < s) red[t] = fmaxf(red[t], red[t + s]);
        __syncthreads();
    }
    float mx = red[0];
    __syncthreads();
    float e = expf(v - mx);
    red[t] = e;
    __syncthreads();
    for (int s = 64; s > 0; s >>= 1) {
        if (t < s) red[t] += red[t + s];
        __syncthreads();
    }
    float inv = 1.f / red[0];
    a[t] = e * inv;
}

__global__ __launch_bounds__(256, 1)
void out_kernel(float* __restrict__ out)
{
    extern __shared__ float sm[];
    const u32 sbase = smem_u32(sm);
    const u32 sAD = sbase + OFF_AD * 4;
    const u32 sVS = sbase + OFF_VS * 4;

    const int tid = threadIdx.x;
    const int tx = tid & 15;
    const int ty = tid >> 4;
    const int tile = blockIdx.x;
    const int b = blockIdx.y;
    const int n0 = tile * TN;
    const bool fullt = (n0 + TN <= NN);

    // a_dup[c][2d] = (a,a)
    for (int idx = tid; idx < NC * NC; idx += 256) {
        int c = idx >> 7, d = idx & 127;
        float v = g_attn[(size_t)b * NC * NC + idx];
        sts64(sAD + (u32)(c * 260 + 2 * d) * 4, pk2(v, v));
    }
    // v tile [d][n] stride-132
    if (fullt) {
        for (int idx = tid; idx < NC * (TN / 4); idx += 256) {
            int d = idx >> 5, q = idx & 31;
            float4 val = *(const float4*)(g_v + ((size_t)b * NC + d) * NN + n0 + q * 4);
            *(float4*)(sm + OFF_VS + d * SROW + q * 4) = val;
        }
    } else {
        for (int idx = tid; idx < NC * TN; idx += 256) {
            int d = idx >> 7, nn = idx & 127;
            int n = n0 + nn;
            sm[OFF_VS + d * SROW + nn] = (n < NN) ? g_v[((size_t)b * NC + d) * NN + n] : 0.f;
        }
    }
    __syncthreads();

    u64 oacc[8][4];
#pragma unroll
    for (int i = 0; i < 8; i++)
#pragma unroll
        for (int j = 0; j < 4; j++) oacc[i][j] = 0ull;

    for (int dq = 0; dq < 64; dq++) {
        u64 ad[8][2];
#pragma unroll
        for (int i = 0; i < 8; i++)
            lds128(ad[i][0], ad[i][1], sAD + (u32)((8 * ty + i) * 260 + 4 * dq) * 4);
        u64 vb[2][2][2];
#pragma unroll
        for (int dd = 0; dd < 2; dd++)
#pragma unroll
            for (int j4 = 0; j4 < 2; j4++)
                lds128(vb[dd][j4][0], vb[dd][j4][1],
                       sVS + (u32)((2 * dq + dd) * SROW + 4 * tx + 64 * j4) * 4);
#pragma unroll
        for (int i = 0; i < 8; i++)
#pragma unroll
            for (int dd = 0; dd < 2; dd++)
#pragma unroll
                for (int j = 0; j < 4; j++)
                    fma2(oacc[i][j], ad[i][dd], vb[dd][j >> 1][j & 1]);
    }

#pragma unroll
    for (int i = 0; i < 8; i++) {
        int c = 8 * ty + i;
#pragma unroll
        for (int j4 = 0; j4 < 2; j4++) {
            float2 pa = upk2(oacc[i][2 * j4]);
            float2 pb = upk2(oacc[i][2 * j4 + 1]);
            int nb = 4 * tx + 64 * j4;
            size_t gaddr = ((size_t)b * NC + c) * NN + n0 + nb;
            if (fullt) {
                float4 v; v.x = pa.x; v.y = pa.y; v.z = pb.x; v.w = pb.y;
                *(float4*)(out + gaddr) = v;
            } else {
                if (n0 + nb < NN)     out[gaddr]     = pa.x;
                if (n0 + nb + 1 < NN) out[gaddr + 1] = pa.y;
                if (n0 + nb + 2 < NN) out[gaddr + 2] = pb.x;
                if (n0 + nb + 3 < NN) out[gaddr + 3] = pb.y;
            }
        }
    }
}

extern "C" void kernel_launch(void* const* d_in, const int* in_sizes, int n_in,
                              void* d_out, int out_size)
{
    const float* pc  = (const float*)d_in[0];
    const float* x   = (const float*)d_in[1];
    const float* Wq  = (const float*)d_in[2];
    const float* gq  = (const float*)d_in[3];
    const float* bq  = (const float*)d_in[4];
    const float* mq  = (const float*)d_in[5];
    const float* vq  = (const float*)d_in[6];
    const float* Wk  = (const float*)d_in[7];
    const float* gk  = (const float*)d_in[8];
    const float* bk  = (const float*)d_in[9];
    const float* mk  = (const float*)d_in[10];
    const float* vk  = (const float*)d_in[11];
    const float* Wv  = (const float*)d_in[12];
    const float* gv  = (const float*)d_in[13];
    const float* bv  = (const float*)d_in[14];
    const float* mv  = (const float*)d_in[15];
    const float* vv  = (const float*)d_in[16];
    const float* Wg1 = (const float*)d_in[17];
    const float* bg1 = (const float*)d_in[18];
    const float* Wg2 = (const float*)d_in[19];
    const float* bg2 = (const float*)d_in[20];
    float* out = (float*)d_out;

    cudaFuncSetAttribute(proj_attn_kernel,
                         cudaFuncAttributeMaxDynamicSharedMemorySize, SMEM_A_BYTES);
    cudaFuncSetAttribute(out_kernel,
                         cudaFuncAttributeMaxDynamicSharedMemorySize, SMEM_O_BYTES);

    prep_kernel<<<1, NC>>>(gq, bq, mq, vq, gk, bk, mk, vk, gv, bv, mv, vv,
                           Wg1, bg1, Wg2, bg2);

    dim3 grid(NT, NB);
    proj_attn_kernel<<<grid, 256, SMEM_A_BYTES>>>(pc, x, Wq, Wk, Wv);
    softmax_kernel<<<NB * NC, NC>>>();
    out_kernel<<<grid, 256, SMEM_O_BYTES>>>(out);
}

// round 6
// speedup vs baseline: 1.1715x; 1.0151x over previous
#include <cuda_runtime.h>
#include <math.h>

#define NB 8
#define NC 128
#define NN 20000
#define TN 128
#define NT 157
#define SROW 132
#define EPSV 1e-5f
#define INVTEMP 0.08838834764831845f  // 1/sqrt(128)

__device__ float g_v[(size_t)NB * NC * NN];      // ~82 MB, layout [b][d][n]
__device__ float g_attn[(size_t)NB * NC * NC];   // 512 KB
__device__ float g_par[11 * NC];

// proj_attn smem float offsets
#define OFF_PC 0          // pc [128][132]
#define OFF_QS 16896      // qs [128][132]
#define OFF_KG 33792      // kg [128][132] (rot-swizzled rows)
#define OFF_WS 50688      // ws [16][132] plain
#define OFF_PAR 52800     // 11*128
#define OFF_X  54208      // [4][128]
#define SMEM_A_FLOATS 54720
#define SMEM_A_BYTES (SMEM_A_FLOATS * 4)   // 218880 B

// out_kernel smem
#define OFF_AS 0          // a [128][132] plain
#define OFF_VS 16896      // v [128][132]
#define SMEM_O_FLOATS 33792
#define SMEM_O_BYTES (SMEM_O_FLOATS * 4)   // 135168 B

typedef unsigned long long u64;
typedef unsigned int u32;

__device__ __forceinline__ u64 pk2(float lo, float hi) {
    u64 r; asm("mov.b64 %0,{%1,%2};" : "=l"(r) : "f"(lo), "f"(hi)); return r;
}
__device__ __forceinline__ u64 dup2(float f) {
    u64 r; asm("mov.b64 %0,{%1,%1};" : "=l"(r) : "f"(f)); return r;
}
__device__ __forceinline__ float2 upk2(u64 v) {
    float2 r; asm("mov.b64 {%0,%1},%2;" : "=f"(r.x), "=f"(r.y) : "l"(v)); return r;
}
__device__ __forceinline__ void fma2(u64& d, u64 a, u64 b) {
    asm("fma.rn.f32x2 %0,%1,%2,%0;" : "+l"(d) : "l"(a), "l"(b));
}
__device__ __forceinline__ u64 lds64(u32 a) {
    u64 r; asm volatile("ld.shared.b64 %0,[%1];" : "=l"(r) : "r"(a)); return r;
}
__device__ __forceinline__ void lds128(u64& x, u64& y, u32 a) {
    asm volatile("ld.shared.v2.u64 {%0,%1},[%2];" : "=l"(x), "=l"(y) : "r"(a));
}
__device__ __forceinline__ void sts64(u32 a, u64 v) {
    asm volatile("st.shared.b64 [%0],%1;" :: "r"(a), "l"(v));
}
__device__ __forceinline__ u32 smem_u32(const void* p) {
    u32 a;
    asm("{.reg .u64 t; cvta.to.shared.u64 t,%1; cvt.u32.u64 %0,t;}" : "=r"(a) : "l"(p));
    return a;
}

// ---- one-time parameter folding ----
__global__ void prep_kernel(const float* __restrict__ gq, const float* __restrict__ bq,
                            const float* __restrict__ mq, const float* __restrict__ vq,
                            const float* __restrict__ gk, const float* __restrict__ bk,
                            const float* __restrict__ mk, const float* __restrict__ vk,
                            const float* __restrict__ gv, const float* __restrict__ bv,
                            const float* __restrict__ mv, const float* __restrict__ vv,
                            const float* __restrict__ Wg1, const float* __restrict__ bg1,
                            const float* __restrict__ Wg2, const float* __restrict__ bg2)
{
    int o = threadIdx.x;
    float s;
    s = gq[o] * rsqrtf(vq[o] + EPSV); g_par[o]       = s; g_par[128 + o] = bq[o] - mq[o] * s;
    s = gk[o] * rsqrtf(vk[o] + EPSV); g_par[256 + o] = s; g_par[384 + o] = bk[o] - mk[o] * s;
    s = gv[o] * rsqrtf(vv[o] + EPSV); g_par[512 + o] = s; g_par[640 + o] = bv[o] - mv[o] * s;
    g_par[768 + o]  = Wg1[o * 2];
    g_par[896 + o]  = Wg1[o * 2 + 1];
    g_par[1024 + o] = Wg2[o * 2];
    g_par[1152 + o] = Wg2[o * 2 + 1];
    g_par[1280 + o] = bg1[o] + bg2[o];
    for (int idx = threadIdx.x; idx < NB * NC * NC; idx += blockDim.x)
        g_attn[idx] = 0.f;
}

// packed 128x128x128 GEMM. out rows o=8*ty+i, cols n = 4*tx + 64*(j>>1) + 2*(j&1).
__device__ __forceinline__ void gemm_f2(const float* __restrict__ Wp,
                                        float* sm, u32 sPC,
                                        int tx, int ty, int tid, u64 acc[8][4])
{
#pragma unroll
    for (int i = 0; i < 8; i++)
#pragma unroll
        for (int j = 0; j < 4; j++) acc[i][j] = 0ull;

    for (int kk = 0; kk < 8; kk++) {
        __syncthreads();   // protect ws from previous consumers
        // stage W[o][kk*16+cc] -> ws[cc][o], plain floats
#pragma unroll
        for (int l = 0; l < 2; l++) {
            int idx = tid + l * 256;
            int o = idx >> 2, cq = idx & 3;
            float4 w = *(const float4*)(Wp + o * NC + kk * 16 + cq * 4);
            float* wsb = sm + OFF_WS + cq * 4 * SROW + o;
            wsb[0]        = w.x;
            wsb[SROW]     = w.y;
            wsb[2 * SROW] = w.z;
            wsb[3 * SROW] = w.w;
        }
        __syncthreads();
#pragma unroll 4
        for (int cc = 0; cc < 16; cc++) {
            // 8 w values for this thread: 2 x LDS.128 (broadcast across tx)
            float4 wa = *(const float4*)(sm + OFF_WS + cc * SROW + 8 * ty);
            float4 wb = *(const float4*)(sm + OFF_WS + cc * SROW + 8 * ty + 4);
            u64 a2[8];
            a2[0] = dup2(wa.x); a2[1] = dup2(wa.y); a2[2] = dup2(wa.z); a2[3] = dup2(wa.w);
            a2[4] = dup2(wb.x); a2[5] = dup2(wb.y); a2[6] = dup2(wb.z); a2[7] = dup2(wb.w);
            u64 b2[4];
            u32 pb = sPC + (u32)((kk * 16 + cc) * SROW + 4 * tx) * 4;
            lds128(b2[0], b2[1], pb);
            lds128(b2[2], b2[3], pb + 64 * 4);
#pragma unroll
            for (int i = 0; i < 8; i++)
#pragma unroll
                for (int j = 0; j < 4; j++)
                    fma2(acc[i][j], a2[i], b2[j]);
        }
    }
}

__global__ __launch_bounds__(256, 1)
void proj_attn_kernel(const float* __restrict__ pc, const float* __restrict__ xin,
                      const float* __restrict__ Wq, const float* __restrict__ Wk,
                      const float* __restrict__ Wv)
{
    extern __shared__ float sm[];
    float* par = sm + OFF_PAR;
    float* x_s = sm + OFF_X;
    const u32 sbase = smem_u32(sm);
    const u32 sPC = sbase + OFF_PC * 4;
    const u32 sQS = sbase + OFF_QS * 4;
    const u32 sKG = sbase + OFF_KG * 4;
    const u32 sX  = sbase + OFF_X * 4;

    const int tid = threadIdx.x;
    const int tx = tid & 15;
    const int ty = tid >> 4;
    const int tile = blockIdx.x;
    const int b = blockIdx.y;
    const int n0 = tile * TN;
    const bool fullt = (n0 + TN <= NN);

    for (int idx = tid; idx < 11 * NC; idx += 256)
        par[idx] = g_par[idx];

    if (fullt) {
        for (int idx = tid; idx < NC * (TN / 4); idx += 256) {
            int c = idx >> 5, q = idx & 31;
            float4 val = *(const float4*)(pc + ((size_t)b * NC + c) * NN + n0 + q * 4);
            *(float4*)(sm + OFF_PC + c * SROW + q * 4) = val;
        }
    } else {
        for (int idx = tid; idx < NC * TN; idx += 256) {
            int c = idx >> 7, nn = idx & 127;
            int n = n0 + nn;
            sm[OFF_PC + c * SROW + nn] = (n < NN) ? pc[((size_t)b * NC + c) * NN + n] : 0.f;
        }
    }
    for (int idx = tid; idx < 4 * TN; idx += 256) {
        int ch = idx >> 7, nn = idx & 127;
        int n = n0 + nn;
        x_s[ch * 128 + nn] = (n < NN) ? xin[((size_t)b * 4 + ch) * NN + n] : 0.f;
    }
    // gemm_f2's first __syncthreads orders fills before use

    u64 acc[8][4];

    // ---- q projection -> qs (BN + relu + /temp) ----
    gemm_f2(Wq, sm, sPC, tx, ty, tid, acc);
#pragma unroll
    for (int i = 0; i < 8; i++) {
        int o = 8 * ty + i;
        float sc = par[o], sh = par[128 + o];
#pragma unroll
        for (int j = 0; j < 4; j++) {
            int nb = 4 * tx + 64 * (j >> 1) + 2 * (j & 1);
            float2 p = upk2(acc[i][j]);
            float v0 = fmaxf(fmaf(p.x, sc, sh), 0.f) * INVTEMP;
            float v1 = fmaxf(fmaf(p.y, sc, sh), 0.f) * INVTEMP;
            if (!fullt) {
                if (n0 + nb >= NN) v0 = 0.f;
                if (n0 + nb + 1 >= NN) v1 = 0.f;
            }
            sts64(sQS + (u32)(o * SROW + nb) * 4, pk2(v0, v1));
        }
    }

    // ---- k projection + graph context -> kg (rot-swizzled rows) ----
    gemm_f2(Wk, sm, sPC, tx, ty, tid, acc);
    {
        u64 xp[4][4];
#pragma unroll
        for (int j = 0; j < 4; j++) {
            int nb = 4 * tx + 64 * (j >> 1) + 2 * (j & 1);
#pragma unroll
            for (int ch = 0; ch < 4; ch++)
                xp[ch][j] = lds64(sX + (u32)(ch * 128 + nb) * 4);
        }
#pragma unroll
        for (int i = 0; i < 8; i++) {
            int o = 8 * ty + i;
            float sc = par[256 + o], sh = par[384 + o];
            u64 w0 = dup2(par[768 + o]);
            u64 w1 = dup2(par[896 + o]);
            u64 w2 = dup2(par[1024 + o]);
            u64 w3 = dup2(par[1152 + o]);
            float bgg = par[1280 + o];
            int rot = 4 * (o & 31);
#pragma unroll
            for (int j = 0; j < 4; j++) {
                int nb = 4 * tx + 64 * (j >> 1) + 2 * (j & 1);
                u64 g2 = dup2(bgg);
                fma2(g2, w0, xp[0][j]);
                fma2(g2, w1, xp[1][j]);
                fma2(g2, w2, xp[2][j]);
                fma2(g2, w3, xp[3][j]);
                float2 gc = upk2(g2);
                float2 p = upk2(acc[i][j]);
                float v0 = fmaxf(fmaf(p.x, sc, sh), 0.f) + gc.x;
                float v1 = fmaxf(fmaf(p.y, sc, sh), 0.f) + gc.y;
                if (!fullt) {
                    if (n0 + nb >= NN) v0 = 0.f;
                    if (n0 + nb + 1 >= NN) v1 = 0.f;
                }
                int phys = (nb + rot) & 127;
                sts64(sKG + (u32)(o * SROW + phys) * 4, pk2(v0, v1));
            }
        }
    }

    // ---- v projection -> g_v[b][d][n] ----
    gemm_f2(Wv, sm, sPC, tx, ty, tid, acc);
#pragma unroll
    for (int i = 0; i < 8; i++) {
        int o = 8 * ty + i;
        float sc = par[512 + o], sh = par[640 + o];
#pragma unroll
        for (int j4 = 0; j4 < 2; j4++) {
            float2 pa = upk2(acc[i][2 * j4]);
            float2 pb = upk2(acc[i][2 * j4 + 1]);
            float4 v;
            v.x = fmaxf(fmaf(pa.x, sc, sh), 0.f);
            v.y = fmaxf(fmaf(pa.y, sc, sh), 0.f);
            v.z = fmaxf(fmaf(pb.x, sc, sh), 0.f);
            v.w = fmaxf(fmaf(pb.y, sc, sh), 0.f);
            int nb = 4 * tx + 64 * j4;
            size_t gaddr = ((size_t)b * NC + o) * NN + n0 + nb;
            if (fullt) {
                *(float4*)(g_v + gaddr) = v;
            } else {
                if (n0 + nb < NN)     g_v[gaddr]     = v.x;
                if (n0 + nb + 1 < NN) g_v[gaddr + 1] = v.y;
                if (n0 + nb + 2 < NN) g_v[gaddr + 2] = v.z;
                if (n0 + nb + 3 < NN) g_v[gaddr + 3] = v.w;
            }
        }
    }

    // ---- attn partial: reduction-packed over n ----
    __syncthreads();
    u64 at[8][8];
#pragma unroll
    for (int i = 0; i < 8; i++)
#pragma unroll
        for (int j = 0; j < 8; j++) at[i][j] = 0ull;

    for (int nq = 0; nq < 32; nq++) {
        u64 qa[8][2];
#pragma unroll
        for (int i = 0; i < 8; i++)
            lds128(qa[i][0], qa[i][1], sQS + (u32)((8 * ty + i) * SROW + 4 * nq) * 4);
#pragma unroll
        for (int h = 0; h < 2; h++) {
            u64 kb[4][2];
#pragma unroll
            for (int jj = 0; jj < 4; jj++) {
                int j = h * 4 + jj;
                int d = tx + 16 * j;
                int phys = (4 * nq + 4 * (d & 31)) & 127;
                lds128(kb[jj][0], kb[jj][1], sKG + (u32)(d * SROW + phys) * 4);
            }
#pragma unroll
            for (int i = 0; i < 8; i++)
#pragma unroll
                for (int jj = 0; jj < 4; jj++) {
                    fma2(at[i][h * 4 + jj], qa[i][0], kb[jj][0]);
                    fma2(at[i][h * 4 + jj], qa[i][1], kb[jj][1]);
                }
        }
    }

#pragma unroll
    for (int i = 0; i < 8; i++) {
        int c = 8 * ty + i;
#pragma unroll
        for (int j = 0; j < 8; j++) {
            int d = tx + 16 * j;
            float2 s = upk2(at[i][j]);
            atomicAdd(&g_attn[((size_t)b * NC + c) * NC + d], s.x + s.y);
        }
    }
}

__global__ void softmax_kernel()
{
    __shared__ float red[NC];
    const int row = blockIdx.x;
    const int t = threadIdx.x;
    float* a = g_attn + (size_t)row * NC;
    float v = a[t];
    red[t] = v;
    __syncthreads();
    for (int s = 64; s > 0; s >>= 1) {
        if (t < s) red[t] = fmaxf(red[t], red[t + s]);
        __syncthreads();
    }
    float mx = red[0];
    __syncthreads();
    float e = expf(v - mx);
    red[t] = e;
    __syncthreads();
    for (int s = 64; s > 0; s >>= 1) {
        if (t < s) red[t] += red[t + s];
        __syncthreads();
    }
    float inv = 1.f / red[0];
    a[t] = e * inv;
}

__global__ __launch_bounds__(256, 1)
void out_kernel(float* __restrict__ out)
{
    extern __shared__ float sm[];
    const u32 sbase = smem_u32(sm);
    const u32 sVS = sbase + OFF_VS * 4;

    const int tid = threadIdx.x;
    const int tx = tid & 15;
    const int ty = tid >> 4;
    const int tile = blockIdx.x;
    const int b = blockIdx.y;
    const int n0 = tile * TN;
    const bool fullt = (n0 + TN <= NN);

    // plain a[c][d] (stride 132)
    for (int idx = tid; idx < NC * NC; idx += 256) {
        int c = idx >> 7, d = idx & 127;
        sm[OFF_AS + c * SROW + d] = g_attn[(size_t)b * NC * NC + idx];
    }
    if (fullt) {
        for (int idx = tid; idx < NC * (TN / 4); idx += 256) {
            int d = idx >> 5, q = idx & 31;
            float4 val = *(const float4*)(g_v + ((size_t)b * NC + d) * NN + n0 + q * 4);
            *(float4*)(sm + OFF_VS + d * SROW + q * 4) = val;
        }
    } else {
        for (int idx = tid; idx < NC * TN; idx += 256) {
            int d = idx >> 7, nn = idx & 127;
            int n = n0 + nn;
            sm[OFF_VS + d * SROW + nn] = (n < NN) ? g_v[((size_t)b * NC + d) * NN + n] : 0.f;
        }
    }
    __syncthreads();

    u64 oacc[8][4];
#pragma unroll
    for (int i = 0; i < 8; i++)
#pragma unroll
        for (int j = 0; j < 4; j++) oacc[i][j] = 0ull;

    for (int dq = 0; dq < 64; dq++) {
        // a pair for d = 2dq, 2dq+1 : one 8-byte load per row + register dup
        float2 av[8];
#pragma unroll
        for (int i = 0; i < 8; i++)
            av[i] = *(const float2*)(sm + OFF_AS + (8 * ty + i) * SROW + 2 * dq);
        u64 vb[2][2][2];
#pragma unroll
        for (int dd = 0; dd < 2; dd++)
#pragma unroll
            for (int j4 = 0; j4 < 2; j4++)
                lds128(vb[dd][j4][0], vb[dd][j4][1],
                       sVS + (u32)((2 * dq + dd) * SROW + 4 * tx + 64 * j4) * 4);
#pragma unroll
        for (int i = 0; i < 8; i++) {
            u64 a0 = dup2(av[i].x);
            u64 a1 = dup2(av[i].y);
#pragma unroll
            for (int j = 0; j < 4; j++) {
                fma2(oacc[i][j], a0, vb[0][j >> 1][j & 1]);
                fma2(oacc[i][j], a1, vb[1][j >> 1][j & 1]);
            }
        }
    }

#pragma unroll
    for (int i = 0; i < 8; i++) {
        int c = 8 * ty + i;
#pragma unroll
        for (int j4 = 0; j4 < 2; j4++) {
            float2 pa = upk2(oacc[i][2 * j4]);
            float2 pb = upk2(oacc[i][2 * j4 + 1]);
            int nb = 4 * tx + 64 * j4;
            size_t gaddr = ((size_t)b * NC + c) * NN + n0 + nb;
            if (fullt) {
                float4 v; v.x = pa.x; v.y = pa.y; v.z = pb.x; v.w = pb.y;
                *(float4*)(out + gaddr) = v;
            } else {
                if (n0 + nb < NN)     out[gaddr]     = pa.x;
                if (n0 + nb + 1 < NN) out[gaddr + 1] = pa.y;
                if (n0 + nb + 2 < NN) out[gaddr + 2] = pb.x;
                if (n0 + nb + 3 < NN) out[gaddr + 3] = pb.y;
            }
        }
    }
}

extern "C" void kernel_launch(void* const* d_in, const int* in_sizes, int n_in,
                              void* d_out, int out_size)
{
    const float* pc  = (const float*)d_in[0];
    const float* x   = (const float*)d_in[1];
    const float* Wq  = (const float*)d_in[2];
    const float* gq  = (const float*)d_in[3];
    const float* bq  = (const float*)d_in[4];
    const float* mq  = (const float*)d_in[5];
    const float* vq  = (const float*)d_in[6];
    const float* Wk  = (const float*)d_in[7];
    const float* gk  = (const float*)d_in[8];
    const float* bk  = (const float*)d_in[9];
    const float* mk  = (const float*)d_in[10];
    const float* vk  = (const float*)d_in[11];
    const float* Wv  = (const float*)d_in[12];
    const float* gv  = (const float*)d_in[13];
    const float* bv  = (const float*)d_in[14];
    const float* mv  = (const float*)d_in[15];
    const float* vv  = (const float*)d_in[16];
    const float* Wg1 = (const float*)d_in[17];
    const float* bg1 = (const float*)d_in[18];
    const float* Wg2 = (const float*)d_in[19];
    const float* bg2 = (const float*)d_in[20];
    float* out = (float*)d_out;

    cudaFuncSetAttribute(proj_attn_kernel,
                         cudaFuncAttributeMaxDynamicSharedMemorySize, SMEM_A_BYTES);
    cudaFuncSetAttribute(out_kernel,
                         cudaFuncAttributeMaxDynamicSharedMemorySize, SMEM_O_BYTES);

    prep_kernel<<<1, NC>>>(gq, bq, mq, vq, gk, bk, mk, vk, gv, bv, mv, vv,
                           Wg1, bg1, Wg2, bg2);

    dim3 grid(NT, NB);
    proj_attn_kernel<<<grid, 256, SMEM_A_BYTES>>>(pc, x, Wq, Wk, Wv);
    softmax_kernel<<<NB * NC, NC>>>();
    out_kernel<<<grid, 256, SMEM_O_BYTES>>>(out);
}